// round 12
// baseline (speedup 1.0000x reference)
#include <cuda_runtime.h>

#define T_TOTAL 34
#define H_OFF   4
#define TN      30     // output timesteps
#define AP      128    // agents per ego group
#define NEGO    32
#define PARTS   4      // CTAs per ego group
#define APC     (AP / PARTS)   // 32 agents per CTA
#define NTHR    256    // 8 octants x 32 agents
#define TPQ     4      // timesteps per octant

// d^2 prefilter: boxes <= 2.0 per side -> corner radius <= sqrt(8).
// Overlap (loss > 0) impossible if center dist > 2*sqrt(8); margin included.
#define D2_THRESH 33.0f

#define NPOS4C (APC * T_TOTAL / 2)   // 544 float4 in this CTA's position slab
#define NHD4C  (APC * T_TOTAL / 4)   // 272 float4 heading slab
#define NVMW4C (APC * T_TOTAL / 4)   // 272 uint4  vm slab (word layout)
#define NVMB4C (APC * T_TOTAL / 16)  //  68 uint4  vm slab (byte layout)

__device__ int          g_viol[NEGO];   // zero-init; reset by last arriver
__device__ unsigned int g_cnt[NEGO];

// max over 4 corners of min(long_t, lat_t) in frame at (px,py) rot (c,s).
__device__ __forceinline__ float corner_loss4(
    const float* cx, const float* cy, float px, float py,
    float c, float s, float bf, float br, float bl, float brt)
{
    float m = -1e30f;
    #pragma unroll
    for (int k = 0; k < 4; k++) {
        float dx = cx[k] - px, dy = cy[k] - py;
        float lx =  dx * c + dy * s;
        float ly = -dx * s + dy * c;
        float lt = fminf(fmaxf(bf  - lx, 0.0f), fmaxf(br  + lx, 0.0f));
        float la = fminf(fmaxf(bl  - ly, 0.0f), fmaxf(brt + ly, 0.0f));
        m = fmaxf(m, fminf(lt, la));
    }
    return m;
}

__global__ void __launch_bounds__(NTHR)
ttc_part(const float* __restrict__ posi,      // [N, 34, 2]
         const float* __restrict__ head,      // [N, 34]
         const float* __restrict__ box,       // [N, 4]  (f, r, l, rt)
         const void*  __restrict__ vm,        // [N, 34] bool (dtype detected)
         float* __restrict__ out)             // [32]
{
    __shared__ float2 s_pxy[T_TOTAL][APC + 1];   // transposed positions
    __shared__ float4 s_hd4[NHD4C];              // raw linear headings
    __shared__ uint4  s_vm4[NVMW4C];             // raw vm (words or bytes)
    __shared__ float  s_ecx[TN][4], s_ecy[TN][4];
    __shared__ float4 s_epose[TN];               // (epx, epy, ce, se)
    __shared__ float4 s_ebox;
    __shared__ float4 s_abox[APC];
    __shared__ unsigned char s_ev[TN];

    const int bid  = blockIdx.x;
    const int b    = bid >> 2;         // ego group
    const int part = bid & 3;          // which 32-agent slice
    const int e    = b * AP;           // ego agent index
    const int g0   = e + part * APC;   // first agent of this CTA
    const int tid  = threadIdx.x;
    const int lane = tid & (APC - 1);  // agent within slice
    const int q    = tid >> 5;         // octant 0..7
    const int tbeg = q * TPQ;

    // ======== SINGLE MLP WINDOW ==============================================
    const unsigned int* w = (const unsigned int*)vm;
    unsigned int dw[8];
    #pragma unroll
    for (int i = 0; i < 8; i++) dw[i] = w[i];

    const float4* pslab = (const float4*)(posi + (size_t)g0 * T_TOTAL * 2);
    float4 pv0 = pslab[tid];
    float4 pv1 = pslab[tid + NTHR];
    float4 pv2; const bool has_p2 = (tid + 2 * NTHR < NPOS4C);   // tid < 32
    if (has_p2) pv2 = pslab[tid + 2 * NTHR];

    const float4* hslab = (const float4*)(head + (size_t)g0 * T_TOTAL);
    float4 hv0 = hslab[tid];
    float4 hv1; const bool has_h1 = (tid + NTHR < NHD4C);        // tid < 16
    if (has_h1) hv1 = hslab[tid + NTHR];

    const uint4* vw = (const uint4*)((const unsigned int*)vm + (size_t)g0 * T_TOTAL);
    uint4 vw0 = vw[tid];
    uint4 vw1; if (has_h1) vw1 = vw[tid + NTHR];
    const uint4* vb = (const uint4*)((const unsigned char*)vm + (size_t)g0 * T_TOTAL);
    uint4 vb0; const bool has_vb = (tid < NVMB4C);               // tid < 68
    if (has_vb) vb0 = vb[tid];

    float4 bv; const bool has_b = (tid < APC);
    if (has_b) bv = *(const float4*)(box + (size_t)(g0 + tid) * 4);

    // ego row (redundant per CTA; ~8 cache lines, broadcast-friendly)
    float2 ep0, ep1; float eyaw; float4 eb_ego;
    unsigned int evw; unsigned char evb;
    if (tid < TN) {
        const int ti  = tid + H_OFF;
        const int ebp = (e * T_TOTAL + ti) * 2;
        ep0 = *(const float2*)(posi + ebp - 2);
        ep1 = *(const float2*)(posi + ebp);
        eyaw   = head[e * T_TOTAL + ti];
        eb_ego = *(const float4*)(box + (size_t)e * 4);
        evw = ((const unsigned int*)vm)[e * T_TOTAL + ti];
        evb = ((const unsigned char*)vm)[e * T_TOTAL + ti];
    }

    // ======== detection (pure ALU) ===========================================
    bool wordmode = true;              // int32/float32 bool: entry = (word != 0)
    #pragma unroll
    for (int i = 0; i < 8; i++)
        wordmode = wordmode && (dw[i] <= 1u || dw[i] == 0x3F800000u);

    // ======== stage ==========================================================
    {
        int k = tid, a = k / 17, t0 = 2 * (k - a * 17);
        s_pxy[t0][a]     = make_float2(pv0.x, pv0.y);
        s_pxy[t0 + 1][a] = make_float2(pv0.z, pv0.w);
        k = tid + NTHR; a = k / 17; t0 = 2 * (k - a * 17);
        s_pxy[t0][a]     = make_float2(pv1.x, pv1.y);
        s_pxy[t0 + 1][a] = make_float2(pv1.z, pv1.w);
        if (has_p2) {
            k = tid + 2 * NTHR; a = k / 17; t0 = 2 * (k - a * 17);
            s_pxy[t0][a]     = make_float2(pv2.x, pv2.y);
            s_pxy[t0 + 1][a] = make_float2(pv2.z, pv2.w);
        }
    }
    if (tid < NHD4C) s_hd4[tid] = hv0;
    if (has_h1)      s_hd4[tid + NTHR] = hv1;
    if (wordmode) {                    // uniform branch
        if (tid < NVMW4C) s_vm4[tid] = vw0;
        if (has_h1)       s_vm4[tid + NTHR] = vw1;
    } else {
        if (has_vb) s_vm4[tid] = vb0;
    }
    if (has_b) s_abox[tid] = bv;

    if (tid < TN) {
        float epx = fmaf(ep1.x - ep0.x, 1.9f, ep1.x);
        float epy = fmaf(ep1.y - ep0.y, 1.9f, ep1.y);
        float ce = cosf(eyaw), se = sinf(eyaw);
        const float lxs[4] = { eb_ego.x,  eb_ego.x, -eb_ego.y, -eb_ego.y };
        const float lys[4] = { eb_ego.z, -eb_ego.w, -eb_ego.w,  eb_ego.z };
        #pragma unroll
        for (int k = 0; k < 4; k++) {
            s_ecx[tid][k] = lxs[k] * ce - lys[k] * se + epx;
            s_ecy[tid][k] = lxs[k] * se + lys[k] * ce + epy;
        }
        s_epose[tid] = make_float4(epx, epy, ce, se);
        s_ev[tid] = wordmode ? (evw != 0u) : (evb != 0);
        if (tid == 0) s_ebox = eb_ego;
    }
    __syncthreads();   // single barrier

    // ======== compute (pure SMEM/ALU) ========================================
    const unsigned int*  vmw_s = (const unsigned int*)s_vm4;
    const unsigned char* vmb_s = (const unsigned char*)s_vm4;
    const float*         hd_s  = (const float*)s_hd4;

    bool viol = false;
    if (!(part == 0 && lane == 0)) {   // the ego itself is an excluded edge
        #pragma unroll
        for (int i = 0; i < TPQ; i++) {
            const int t = tbeg + i;
            if (t >= TN) break;        // uniform (octant 7 only)
            const int ti = t + H_OFF;

            float2 p0 = s_pxy[ti - 1][lane];
            float2 p1 = s_pxy[ti][lane];
            float apx = fmaf(p1.x - p0.x, 1.9f, p1.x);
            float apy = fmaf(p1.y - p0.y, 1.9f, p1.y);

            float4 ep = s_epose[t];
            float ddx = apx - ep.x, ddy = apy - ep.y;
            if (fmaf(ddx, ddx, ddy * ddy) > D2_THRESH) continue;  // ~99% reject

            bool valid = s_ev[t] && (wordmode ? (vmw_s[lane * T_TOTAL + ti] != 0u)
                                              : (vmb_s[lane * T_TOTAL + ti] != 0));
            if (!valid) continue;

            float ayaw = hd_s[lane * T_TOTAL + ti];
            float4 ab  = s_abox[lane];
            float ca = cosf(ayaw), sa = sinf(ayaw);

            float ecx[4], ecy[4];
            #pragma unroll
            for (int k = 0; k < 4; k++) { ecx[k] = s_ecx[t][k]; ecy[k] = s_ecy[t][k]; }
            float L1 = corner_loss4(ecx, ecy, apx, apy, ca, sa,
                                    ab.x, ab.y, ab.z, ab.w);

            float acx[4], acy[4];
            const float lxs[4] = { ab.x,  ab.x, -ab.y, -ab.y };
            const float lys[4] = { ab.z, -ab.w, -ab.w,  ab.z };
            #pragma unroll
            for (int k = 0; k < 4; k++) {
                acx[k] = lxs[k] * ca - lys[k] * sa + apx;
                acy[k] = lxs[k] * sa + lys[k] * ca + apy;
            }
            float4 eb = s_ebox;
            float L2 = corner_loss4(acx, acy, ep.x, ep.y, ep.z, ep.w,
                                    eb.x, eb.y, eb.z, eb.w);

            viol = viol || (fmaxf(L1, L2) > 0.0f);
        }
    }

    // ======== combine across the 4 CTAs of this ego ==========================
    int any = __syncthreads_or(viol ? 1 : 0);
    if (tid == 0) {
        if (any) atomicOr(&g_viol[b], 1);
        __threadfence();
        unsigned int prev = atomicAdd(&g_cnt[b], 1u);
        if (prev == PARTS - 1) {       // last arriver finalizes
            __threadfence();
            int v = atomicAdd(&g_viol[b], 0);   // ordered read
            out[b] = v ? 0.0f : 1.0f;
            g_viol[b] = 0;             // reset for next graph replay
            g_cnt[b]  = 0;
        }
    }
}

extern "C" void kernel_launch(void* const* d_in, const int* in_sizes, int n_in,
                              void* d_out, int out_size) {
    const float* posi = (const float*)d_in[0];   // infer_position
    const float* head = (const float*)d_in[1];   // infer_heading
    const float* box  = (const float*)d_in[2];   // box
    const void*  vm   = (const void*)d_in[3];    // infer_valid_mask
    float* out = (float*)d_out;

    ttc_part<<<NEGO * PARTS, NTHR>>>(posi, head, box, vm, out);
}